// round 15
// baseline (speedup 1.0000x reference)
#include <cuda_runtime.h>
#include <math.h>
#include <stdint.h>

#define NB 32
#define NC 64
#define NN 1024
#define NK 10
#define NO 1024
#define NKC 640            // NK * NC
#define EPSN 1e-5f

// TF32 quantization (cublas-style input rounding)
__device__ __forceinline__ float tf32r(float a) {
    asm("cvt.rna.tf32.f32 %0, %1;" : "=f"(a) : "f"(a));
    return a;
}

// cp.async helpers (16-byte, L2-bypass-L1 variant)
__device__ __forceinline__ void cp_async16(void* smem, const void* gmem) {
    uint32_t s = (uint32_t)__cvta_generic_to_shared(smem);
    asm volatile("cp.async.cg.shared.global [%0], [%1], 16;" :: "r"(s), "l"(gmem));
}
#define CP_COMMIT() asm volatile("cp.async.commit_group;")
#define CP_WAIT0()  asm volatile("cp.async.wait_group 0;")

// ---------------- scratch (device globals: allocation-free) ----------------
__device__ float g_xt[NB * NN * NC];            // x transposed: [b][n][c]
__device__ float g_xx[NB * NN];                 // sum of squares per point
__device__ float g_nd[NB * NN * NN];            // neg_dist (134 MB)
__device__ int   g_idx[NB * NN * NK];           // top-k indices
__device__ float g_feat[NB * NN * NKC];         // gathered features (TF32-quantized)
__device__ float g_w1t[NO * 1024];              // tf32r(w1)
__device__ float g_w2t[NO * 1024];              // tf32r(w2)
__device__ float g_y1[NB * NO * NKC];           // GEMM1 out (fp32)
__device__ float g_y1t[NB * NO * NKC];          // tf32r(relu(bn1(y1)))
__device__ float g_y2[NB * NO * NKC];           // GEMM2 out
__device__ float g_a1[NO], g_c1[NO], g_a2[NO], g_c2[NO];  // BN scale/shift

// ---------------- transpose x (B,C,N) -> xt (B,N,C) ----------------
__global__ void transpose_kernel(const float* __restrict__ x) {
    __shared__ float tile[32][33];
    int b  = blockIdx.z;
    int c0 = blockIdx.y * 32;
    int n0 = blockIdx.x * 32;
    int tx = threadIdx.x, ty = threadIdx.y;   // 32 x 8
    const float* xb = x + b * NC * NN;
#pragma unroll
    for (int i = 0; i < 32; i += 8)
        tile[ty + i][tx] = xb[(c0 + ty + i) * NN + n0 + tx];
    __syncthreads();
    float* xtb = g_xt + b * NN * NC;
#pragma unroll
    for (int i = 0; i < 32; i += 8)
        xtb[(n0 + ty + i) * NC + c0 + tx] = tile[tx][ty + i];
}

// ---------------- xx[b,n]: WINNING RECIPE (bit-frozen) ----------------------
__global__ void xx_kernel(const float* __restrict__ x) {
    int t = blockIdx.x * blockDim.x + threadIdx.x;   // 32768 threads
    int b = t >> 10, n = t & 1023;
    const float* xb = x + b * NC * NN + n;
    float a0 = 0.f, a1 = 0.f, a2 = 0.f, a3 = 0.f;
#pragma unroll
    for (int i = 0; i < 16; i++) {
        float v0 = xb[(4 * i + 0) * NN];
        float v1 = xb[(4 * i + 1) * NN];
        float v2 = xb[(4 * i + 2) * NN];
        float v3 = xb[(4 * i + 3) * NN];
        a0 = __fadd_rn(a0, __fmul_rn(v0, v0));
        a1 = __fadd_rn(a1, __fmul_rn(v1, v1));
        a2 = __fadd_rn(a2, __fmul_rn(v2, v2));
        a3 = __fadd_rn(a3, __fmul_rn(v3, v3));
    }
    g_xx[t] = __fadd_rn(__fadd_rn(a0, a2), __fadd_rn(a1, a3));
}

// ---------------- neg_dist: SYMMETRIC tiles (bit-exact halving, frozen) -----
__global__ void dist_kernel() {
    __shared__ float sn[64][65];
    __shared__ float sm[64][65];
    __shared__ float sxn[64], sxm[64];
    int b = blockIdx.z;
    int p = blockIdx.x;
    int ti = 0;
    while (p >= 16 - ti) { p -= 16 - ti; ti++; }
    int tj = ti + p;
    int n0 = ti * 64, m0 = tj * 64;

    int tid = threadIdx.x;
    const float* xt = g_xt + b * NN * NC;
    for (int i = tid; i < 4096; i += 256) {
        int r = i >> 6, c = i & 63;
        sn[r][c] = xt[(n0 + r) * NC + c];
        sm[r][c] = xt[(m0 + r) * NC + c];
    }
    if (tid < 64)            sxn[tid]      = g_xx[b * NN + n0 + tid];
    else if (tid < 128)      sxm[tid - 64] = g_xx[b * NN + m0 + tid - 64];
    __syncthreads();

    int tx = tid & 15, ty = tid >> 4;
    float acc[4][4] = {};
#pragma unroll
    for (int c = 0; c < 64; c++) {
        float rn[4], rm[4];
#pragma unroll
        for (int i = 0; i < 4; i++) { rn[i] = sn[ty * 4 + i][c]; rm[i] = sm[tx * 4 + i][c]; }
#pragma unroll
        for (int i = 0; i < 4; i++)
#pragma unroll
            for (int j = 0; j < 4; j++) acc[i][j] = __fmaf_rn(rn[i], rm[j], acc[i][j]);
    }
#pragma unroll
    for (int i = 0; i < 4; i++) {
        float xn = sxn[ty * 4 + i];
        float4 o;
        o.x = __fsub_rn(__fsub_rn(__fmul_rn(2.f, acc[i][0]), xn), sxm[tx * 4 + 0]);
        o.y = __fsub_rn(__fsub_rn(__fmul_rn(2.f, acc[i][1]), xn), sxm[tx * 4 + 1]);
        o.z = __fsub_rn(__fsub_rn(__fmul_rn(2.f, acc[i][2]), xn), sxm[tx * 4 + 2]);
        o.w = __fsub_rn(__fsub_rn(__fmul_rn(2.f, acc[i][3]), xn), sxm[tx * 4 + 3]);
        *(float4*)&g_nd[(size_t)(b * NN + n0 + ty * 4 + i) * NN + m0 + tx * 4] = o;
    }
    if (ti == tj) return;
    __syncthreads();
#pragma unroll
    for (int i = 0; i < 4; i++) {
        float xn = sxn[ty * 4 + i];
#pragma unroll
        for (int j = 0; j < 4; j++) {
            float mv = __fsub_rn(__fsub_rn(__fmul_rn(2.f, acc[i][j]),
                                           sxm[tx * 4 + j]), xn);
            sm[tx * 4 + j][ty * 4 + i] = mv;
        }
    }
    __syncthreads();
    for (int i = tid; i < 4096; i += 256) {
        int r = i >> 6, c = i & 63;
        g_nd[(size_t)(b * NN + m0 + r) * NN + n0 + c] = sm[r][c];
    }
}

// ---------------- top-K: incremental per-lane rescan (same selection) -------
// Per round, only the winning lane rescans its 32 values; all other lanes'
// local argmaxes are unchanged. Ordering/tie semantics identical to R13/14.
__global__ void topk_kernel() {
    int w    = (blockIdx.x * blockDim.x + threadIdx.x) >> 5;  // row id 0..32767
    int lane = threadIdx.x & 31;
    const float* row = g_nd + (size_t)w * NN;
    float v[32];
#pragma unroll
    for (int j = 0; j < 32; j++) v[j] = row[j * 32 + lane];
    unsigned used = 0u;
    float lmax = v[0]; int lj = 0;
#pragma unroll
    for (int j = 1; j < 32; j++)
        if (v[j] > lmax) { lmax = v[j]; lj = j; }
#pragma unroll
    for (int t = 0; t < NK; t++) {
        float bv = lmax; int bi = lj * 32 + lane;
#pragma unroll
        for (int off = 16; off; off >>= 1) {
            float ov = __shfl_xor_sync(0xffffffffu, bv, off);
            int   oi = __shfl_xor_sync(0xffffffffu, bi, off);
            if (ov > bv || (ov == bv && oi < bi)) { bv = ov; bi = oi; }
        }
        if (lane == 0) g_idx[w * NK + t] = bi;
        if (t < NK - 1 && (bi & 31) == lane) {
            used |= 1u << (bi >> 5);
            lmax = -3.4e38f; lj = 0;
#pragma unroll
            for (int j = 0; j < 32; j++)
                if (!((used >> j) & 1u) && v[j] > lmax) { lmax = v[j]; lj = j; }
        }
    }
}

// ---------------- gather: feat = tf32r(xt[idx]) (pre-quantized for mma) -----
__global__ void gather_kernel() {
    int t = blockIdx.x * blockDim.x + threadIdx.x;
    int c = t & 63;
    int k = (t >> 6) % NK;
    int n = (t / NKC) & 1023;
    int b = t / (NN * NKC);
    int gi = g_idx[((b << 10) + n) * NK + k];
    g_feat[t] = tf32r(g_xt[((b << 10) + gi) * NC + c]);
}

// ---------------- weight pre-quantization: dst = tf32r(w) -------------------
template <int WHICH>
__global__ void quantw_kernel(const float* __restrict__ w) {
    float* dst = (WHICH == 1) ? g_w1t : g_w2t;
    int t = blockIdx.x * blockDim.x + threadIdx.x;      // NO*1024/4 float4s
    float4 v = ((const float4*)w)[t];
    v.x = tf32r(v.x); v.y = tf32r(v.y); v.z = tf32r(v.z); v.w = tf32r(v.w);
    ((float4*)dst)[t] = v;
}

// ---------------- bn_apply: y1t = tf32r(relu(a1*y1 + c1)) -------------------
__global__ void bn_apply_kernel() {
    int t = blockIdx.x * blockDim.x + threadIdx.x;      // 5,242,880 float4s
    int o = (t / (NKC / 4)) % NO;
    float a = g_a1[o], c = g_c1[o];
    float4 v = ((const float4*)g_y1)[t];
    v.x = tf32r(fmaxf(fmaf(a, v.x, c), 0.f));
    v.y = tf32r(fmaxf(fmaf(a, v.y, c), 0.f));
    v.z = tf32r(fmaxf(fmaf(a, v.z, c), 0.f));
    v.w = tf32r(fmaxf(fmaf(a, v.w, c), 0.f));
    ((float4*)g_y1t)[t] = v;
}

// ---------------- layer GEMMs: cp.async double-buffered TF32 mma ------------
// Inputs pre-quantized (tf32 bit patterns) -> hot loop is pure LDS + HMMA.
// Block: 128(o) x 64(kc) x 2 batches, k-tile 16, 2-stage pipeline.
__device__ __forceinline__ void mma_tf32(float* d, const uint32_t* a,
                                         const uint32_t* b, const float* c) {
    asm volatile(
        "mma.sync.aligned.m16n8k8.row.col.f32.tf32.tf32.f32 "
        "{%0,%1,%2,%3}, {%4,%5,%6,%7}, {%8,%9}, {%10,%11,%12,%13};"
        : "=f"(d[0]), "=f"(d[1]), "=f"(d[2]), "=f"(d[3])
        : "r"(a[0]), "r"(a[1]), "r"(a[2]), "r"(a[3]),
          "r"(b[0]), "r"(b[1]),
          "f"(c[0]), "f"(c[1]), "f"(c[2]), "f"(c[3]));
}

template <int STAGE>
__global__ __launch_bounds__(256) void gemm_mma_kernel() {
    __shared__ float As[2][128][20];      // pad 20: (4g+tg) unique -> no conflicts
    __shared__ float Bs[2][2][16][72];    // pad 72: (8tg+g) unique -> no conflicts
    const float* A  = (STAGE == 1) ? g_w1t : g_w2t;
    const float* Bm = (STAGE == 1) ? g_feat : g_y1t;
    float*       Cm = (STAGE == 1) ? g_y1   : g_y2;

    int tid = threadIdx.x;                    // 256
    int bz0 = blockIdx.z * 2;
    int o0  = blockIdx.y * 128;
    int kc0 = blockIdx.x * 64;
    const float* Ab  = A + (size_t)o0 * 1024;
    const float* Bb0 = Bm + (size_t)(bz0    ) * (NO * NKC) + kc0;
    const float* Bb1 = Bm + (size_t)(bz0 + 1) * (NO * NKC) + kc0;

    int warp = tid >> 5, lane = tid & 31;
    int warp_o = warp & 3, warp_n = warp >> 2;   // 4 x 2 warp grid
    int g = lane >> 2, tg = lane & 3;

    // per-thread load coordinates
    int a_row0 = tid >> 2,            a_col = (tid & 3) * 4;          // +0, +64 rows
    int b_row  = tid >> 4,            b_col = (tid & 15) * 4;

    float acc[2][2][4][4];
#pragma unroll
    for (int q = 0; q < 2; q++)
#pragma unroll
        for (int mt = 0; mt < 2; mt++)
#pragma unroll
            for (int nt = 0; nt < 4; nt++)
#pragma unroll
                for (int r = 0; r < 4; r++) acc[q][mt][nt][r] = 0.f;

#define LOAD_TILE(kt, buf)                                                      \
    {                                                                           \
        int k0 = (kt) * 16;                                                     \
        cp_async16(&As[buf][a_row0     ][a_col],                                \
                   Ab + (size_t)(a_row0     ) * 1024 + k0 + a_col);             \
        cp_async16(&As[buf][a_row0 + 64][a_col],                                \
                   Ab + (size_t)(a_row0 + 64) * 1024 + k0 + a_col);             \
        cp_async16(&Bs[buf][0][b_row][b_col],                                   \
                   Bb0 + (size_t)(k0 + b_row) * NKC + b_col);                   \
        cp_async16(&Bs[buf][1][b_row][b_col],                                   \
                   Bb1 + (size_t)(k0 + b_row) * NKC + b_col);                   \
    }

    LOAD_TILE(0, 0);
    CP_COMMIT();
    CP_WAIT0();
    __syncthreads();

    for (int kt = 0; kt < 64; kt++) {
        int cur = kt & 1;
        if (kt < 63) { LOAD_TILE(kt + 1, cur ^ 1); CP_COMMIT(); }
#pragma unroll
        for (int s = 0; s < 2; s++) {
            int kr = s * 8;
            uint32_t af[2][4];
#pragma unroll
            for (int mt = 0; mt < 2; mt++) {
                int o = warp_o * 32 + mt * 16;
                af[mt][0] = __float_as_uint(As[cur][o + g    ][kr + tg    ]);
                af[mt][1] = __float_as_uint(As[cur][o + g + 8][kr + tg    ]);
                af[mt][2] = __float_as_uint(As[cur][o + g    ][kr + tg + 4]);
                af[mt][3] = __float_as_uint(As[cur][o + g + 8][kr + tg + 4]);
            }
#pragma unroll
            for (int q = 0; q < 2; q++) {
                uint32_t bf[4][2];
#pragma unroll
                for (int nt = 0; nt < 4; nt++) {
                    int col = warp_n * 32 + nt * 8 + g;
                    bf[nt][0] = __float_as_uint(Bs[cur][q][kr + tg    ][col]);
                    bf[nt][1] = __float_as_uint(Bs[cur][q][kr + tg + 4][col]);
                }
#pragma unroll
                for (int mt = 0; mt < 2; mt++)
#pragma unroll
                    for (int nt = 0; nt < 4; nt++)
                        mma_tf32(acc[q][mt][nt], af[mt], bf[nt], acc[q][mt][nt]);
            }
        }
        if (kt < 63) CP_WAIT0();
        __syncthreads();
    }
#undef LOAD_TILE

#pragma unroll
    for (int q = 0; q < 2; q++) {
        float* Cb = Cm + (size_t)(bz0 + q) * (NO * NKC) + (size_t)o0 * NKC + kc0;
#pragma unroll
        for (int mt = 0; mt < 2; mt++) {
            int row = warp_o * 32 + mt * 16 + g;
#pragma unroll
            for (int nt = 0; nt < 4; nt++) {
                int col = warp_n * 32 + nt * 8 + tg * 2;
                *(float2*)&Cb[(size_t)(row    ) * NKC + col] =
                    make_float2(acc[q][mt][nt][0], acc[q][mt][nt][1]);
                *(float2*)&Cb[(size_t)(row + 8) * NKC + col] =
                    make_float2(acc[q][mt][nt][2], acc[q][mt][nt][3]);
            }
        }
    }
}

// ---------------- BN stats per channel o: a = gamma*rsqrt(var+eps), c = beta - mean*a
__global__ void bn_stats_kernel(const float* __restrict__ gamma,
                                const float* __restrict__ beta, int which) {
    const float* Y = which ? g_y2 : g_y1;
    int o = blockIdx.x, tid = threadIdx.x;
    float s = 0.f, sq = 0.f;
    for (int j = tid; j < NB * NKC; j += 256) {
        int b = j / NKC, kc = j - b * NKC;
        float v = Y[((size_t)b * NO + o) * NKC + kc];
        s += v; sq = fmaf(v, v, sq);
    }
    __shared__ float ss[256], s2[256];
    ss[tid] = s; s2[tid] = sq;
    __syncthreads();
    for (int st = 128; st; st >>= 1) {
        if (tid < st) { ss[tid] += ss[tid + st]; s2[tid] += s2[tid + st]; }
        __syncthreads();
    }
    if (tid == 0) {
        float cnt  = (float)(NB * NKC);
        float mean = ss[0] / cnt;
        float var  = fmaxf(s2[0] / cnt - mean * mean, 0.f);
        float ai   = gamma[o] * rsqrtf(var + EPSN);
        if (which) { g_a2[o] = ai; g_c2[o] = beta[o] - mean * ai; }
        else       { g_a1[o] = ai; g_c1[o] = beta[o] - mean * ai; }
    }
}

// ---------------- out[b,o,c] = max_k relu(a2*y2 + c2) ----------------
__global__ void max_kernel(float* __restrict__ out) {
    int t = blockIdx.x * blockDim.x + threadIdx.x;
    int c = t & 63;
    int o = (t >> 6) & 1023;
    int b = t >> 16;
    const float* y = g_y2 + ((size_t)(b * NO + o)) * NKC + c;
    float a = g_a2[o], cc = g_c2[o];
    float m = -3.4e38f;
#pragma unroll
    for (int k = 0; k < NK; k++) m = fmaxf(m, fmaf(a, y[k * 64], cc));
    out[t] = fmaxf(m, 0.f);
}

// ---------------- launch ----------------
extern "C" void kernel_launch(void* const* d_in, const int* in_sizes, int n_in,
                              void* d_out, int out_size) {
    const float* x      = (const float*)d_in[0];
    const float* w1     = (const float*)d_in[1];
    // b1 = d_in[2], b2 = d_in[6]: zeros AND cancelled by BN mean-subtraction
    const float* gamma1 = (const float*)d_in[3];
    const float* beta1  = (const float*)d_in[4];
    const float* w2     = (const float*)d_in[5];
    const float* gamma2 = (const float*)d_in[7];
    const float* beta2  = (const float*)d_in[8];
    float* out = (float*)d_out;

    transpose_kernel<<<dim3(32, 2, 32), dim3(32, 8)>>>(x);
    xx_kernel<<<128, 256>>>(x);
    quantw_kernel<1><<<1024, 256>>>(w1);
    quantw_kernel<2><<<1024, 256>>>(w2);
    dist_kernel<<<dim3(136, 1, 32), 256>>>();
    topk_kernel<<<4096, 256>>>();
    gather_kernel<<<81920, 256>>>();
    gemm_mma_kernel<1><<<dim3(10, 8, 16), 256>>>();
    bn_stats_kernel<<<1024, 256>>>(gamma1, beta1, 0);
    bn_apply_kernel<<<20480, 256>>>();
    gemm_mma_kernel<2><<<dim3(10, 8, 16), 256>>>();
    bn_stats_kernel<<<1024, 256>>>(gamma2, beta2, 1);
    max_kernel<<<8192, 256>>>(out);
}

// round 16
// speedup vs baseline: 1.0125x; 1.0125x over previous
#include <cuda_runtime.h>
#include <math.h>
#include <stdint.h>

#define NB 32
#define NC 64
#define NN 1024
#define NK 10
#define NO 1024
#define NKC 640            // NK * NC
#define EPSN 1e-5f

// TF32 quantization (cublas-style input rounding)
__device__ __forceinline__ float tf32r(float a) {
    asm("cvt.rna.tf32.f32 %0, %1;" : "=f"(a) : "f"(a));
    return a;
}

// ---------------- scratch (device globals: allocation-free) ----------------
__device__ float g_xt[NB * NN * NC];            // x transposed: [b][n][c]
__device__ float g_xx[NB * NN];                 // sum of squares per point
__device__ float g_nd[NB * NN * NN];            // neg_dist (134 MB)
__device__ int   g_idx[NB * NN * NK];           // top-k indices
__device__ float g_feat[NB * NN * NKC];         // gathered features [b][n][k*64+c]
__device__ float g_y1[NB * NO * NKC];           // GEMM1 out [b][o][kc]
__device__ float g_y2[NB * NO * NKC];           // GEMM2 out
__device__ float g_a1[NO], g_c1[NO], g_a2[NO], g_c2[NO];  // BN scale/shift

// ---------------- transpose x (B,C,N) -> xt (B,N,C) ----------------
__global__ void transpose_kernel(const float* __restrict__ x) {
    __shared__ float tile[32][33];
    int b  = blockIdx.z;
    int c0 = blockIdx.y * 32;
    int n0 = blockIdx.x * 32;
    int tx = threadIdx.x, ty = threadIdx.y;   // 32 x 8
    const float* xb = x + b * NC * NN;
#pragma unroll
    for (int i = 0; i < 32; i += 8)
        tile[ty + i][tx] = xb[(c0 + ty + i) * NN + n0 + tx];
    __syncthreads();
    float* xtb = g_xt + b * NN * NC;
#pragma unroll
    for (int i = 0; i < 32; i += 8)
        xtb[(n0 + ty + i) * NC + c0 + tx] = tile[tx][ty + i];
}

// ---------------- xx[b,n]: WINNING RECIPE (bit-frozen) ----------------------
__global__ void xx_kernel(const float* __restrict__ x) {
    int t = blockIdx.x * blockDim.x + threadIdx.x;   // 32768 threads
    int b = t >> 10, n = t & 1023;
    const float* xb = x + b * NC * NN + n;
    float a0 = 0.f, a1 = 0.f, a2 = 0.f, a3 = 0.f;
#pragma unroll
    for (int i = 0; i < 16; i++) {
        float v0 = xb[(4 * i + 0) * NN];
        float v1 = xb[(4 * i + 1) * NN];
        float v2 = xb[(4 * i + 2) * NN];
        float v3 = xb[(4 * i + 3) * NN];
        a0 = __fadd_rn(a0, __fmul_rn(v0, v0));
        a1 = __fadd_rn(a1, __fmul_rn(v1, v1));
        a2 = __fadd_rn(a2, __fmul_rn(v2, v2));
        a3 = __fadd_rn(a3, __fmul_rn(v3, v3));
    }
    g_xx[t] = __fadd_rn(__fadd_rn(a0, a2), __fadd_rn(a1, a3));
}

// ---------------- neg_dist: SYMMETRIC tiles (bit-exact halving, frozen) -----
__global__ void dist_kernel() {
    __shared__ float sn[64][65];
    __shared__ float sm[64][65];
    __shared__ float sxn[64], sxm[64];
    int b = blockIdx.z;
    int p = blockIdx.x;
    int ti = 0;
    while (p >= 16 - ti) { p -= 16 - ti; ti++; }
    int tj = ti + p;
    int n0 = ti * 64, m0 = tj * 64;

    int tid = threadIdx.x;
    const float* xt = g_xt + b * NN * NC;
    for (int i = tid; i < 4096; i += 256) {
        int r = i >> 6, c = i & 63;
        sn[r][c] = xt[(n0 + r) * NC + c];
        sm[r][c] = xt[(m0 + r) * NC + c];
    }
    if (tid < 64)            sxn[tid]      = g_xx[b * NN + n0 + tid];
    else if (tid < 128)      sxm[tid - 64] = g_xx[b * NN + m0 + tid - 64];
    __syncthreads();

    int tx = tid & 15, ty = tid >> 4;
    float acc[4][4] = {};
#pragma unroll
    for (int c = 0; c < 64; c++) {
        float rn[4], rm[4];
#pragma unroll
        for (int i = 0; i < 4; i++) { rn[i] = sn[ty * 4 + i][c]; rm[i] = sm[tx * 4 + i][c]; }
#pragma unroll
        for (int i = 0; i < 4; i++)
#pragma unroll
            for (int j = 0; j < 4; j++) acc[i][j] = __fmaf_rn(rn[i], rm[j], acc[i][j]);
    }
#pragma unroll
    for (int i = 0; i < 4; i++) {
        float xn = sxn[ty * 4 + i];
        float4 o;
        o.x = __fsub_rn(__fsub_rn(__fmul_rn(2.f, acc[i][0]), xn), sxm[tx * 4 + 0]);
        o.y = __fsub_rn(__fsub_rn(__fmul_rn(2.f, acc[i][1]), xn), sxm[tx * 4 + 1]);
        o.z = __fsub_rn(__fsub_rn(__fmul_rn(2.f, acc[i][2]), xn), sxm[tx * 4 + 2]);
        o.w = __fsub_rn(__fsub_rn(__fmul_rn(2.f, acc[i][3]), xn), sxm[tx * 4 + 3]);
        *(float4*)&g_nd[(size_t)(b * NN + n0 + ty * 4 + i) * NN + m0 + tx * 4] = o;
    }
    if (ti == tj) return;
    __syncthreads();
#pragma unroll
    for (int i = 0; i < 4; i++) {
        float xn = sxn[ty * 4 + i];
#pragma unroll
        for (int j = 0; j < 4; j++) {
            float mv = __fsub_rn(__fsub_rn(__fmul_rn(2.f, acc[i][j]),
                                           sxm[tx * 4 + j]), xn);
            sm[tx * 4 + j][ty * 4 + i] = mv;
        }
    }
    __syncthreads();
    for (int i = tid; i < 4096; i += 256) {
        int r = i >> 6, c = i & 63;
        g_nd[(size_t)(b * NN + m0 + r) * NN + n0 + c] = sm[r][c];
    }
}

// ---------------- top-K: incremental per-lane rescan (KEPT from R15) --------
__global__ void topk_kernel() {
    int w    = (blockIdx.x * blockDim.x + threadIdx.x) >> 5;  // row id 0..32767
    int lane = threadIdx.x & 31;
    const float* row = g_nd + (size_t)w * NN;
    float v[32];
#pragma unroll
    for (int j = 0; j < 32; j++) v[j] = row[j * 32 + lane];
    unsigned used = 0u;
    float lmax = v[0]; int lj = 0;
#pragma unroll
    for (int j = 1; j < 32; j++)
        if (v[j] > lmax) { lmax = v[j]; lj = j; }
#pragma unroll
    for (int t = 0; t < NK; t++) {
        float bv = lmax; int bi = lj * 32 + lane;
#pragma unroll
        for (int off = 16; off; off >>= 1) {
            float ov = __shfl_xor_sync(0xffffffffu, bv, off);
            int   oi = __shfl_xor_sync(0xffffffffu, bi, off);
            if (ov > bv || (ov == bv && oi < bi)) { bv = ov; bi = oi; }
        }
        if (lane == 0) g_idx[w * NK + t] = bi;
        if (t < NK - 1 && (bi & 31) == lane) {
            used |= 1u << (bi >> 5);
            lmax = -3.4e38f; lj = 0;
#pragma unroll
            for (int j = 0; j < 32; j++)
                if (!((used >> j) & 1u) && v[j] > lmax) { lmax = v[j]; lj = j; }
        }
    }
}

// ---------------- gather feat[b][n][k*64+c] = xt[b][idx[b,n,k]][c] ----------------
__global__ void gather_kernel() {
    int t = blockIdx.x * blockDim.x + threadIdx.x;
    int c = t & 63;
    int k = (t >> 6) % NK;
    int n = (t / NKC) & 1023;
    int b = t / (NN * NKC);
    int gi = g_idx[((b << 10) + n) * NK + k];
    g_feat[t] = g_xt[((b << 10) + gi) * NC + c];
}

// ---------------- layer GEMMs: mma.sync TF32, 2 batches/block (R14 form) ----
__device__ __forceinline__ void mma_tf32(float* d, const uint32_t* a,
                                         const uint32_t* b, const float* c) {
    asm volatile(
        "mma.sync.aligned.m16n8k8.row.col.f32.tf32.tf32.f32 "
        "{%0,%1,%2,%3}, {%4,%5,%6,%7}, {%8,%9}, {%10,%11,%12,%13};"
        : "=f"(d[0]), "=f"(d[1]), "=f"(d[2]), "=f"(d[3])
        : "r"(a[0]), "r"(a[1]), "r"(a[2]), "r"(a[3]),
          "r"(b[0]), "r"(b[1]),
          "f"(c[0]), "f"(c[1]), "f"(c[2]), "f"(c[3]));
}

template <int STAGE>
__global__ __launch_bounds__(256) void gemm_mma_kernel(const float* __restrict__ A) {
    __shared__ float As[128][36];      // [o][k]
    __shared__ float Bs[2][32][72];    // [q][k][kc]
    const float* Bm = (STAGE == 1) ? g_feat : g_y1;
    float*       Cm = (STAGE == 1) ? g_y1   : g_y2;

    int tid = threadIdx.x;                    // 256
    int bz0 = blockIdx.z * 2;                 // batches bz0, bz0+1
    int o0  = blockIdx.y * 128;
    int kc0 = blockIdx.x * 64;
    const float* Ab = A + (size_t)o0 * 1024;
    const float* Bb0 = Bm + (size_t)(bz0    ) * (NO * NKC) + kc0;
    const float* Bb1 = Bm + (size_t)(bz0 + 1) * (NO * NKC) + kc0;

    int warp = tid >> 5, lane = tid & 31;
    int warp_o = warp & 3, warp_n = warp >> 2;   // 4 x 2 warp grid
    int g = lane >> 2, tg = lane & 3;

    float acc[2][2][4][4];                    // [q][mt][nt][reg]
#pragma unroll
    for (int q = 0; q < 2; q++)
#pragma unroll
        for (int mt = 0; mt < 2; mt++)
#pragma unroll
            for (int nt = 0; nt < 4; nt++)
#pragma unroll
                for (int r = 0; r < 4; r++) acc[q][mt][nt][r] = 0.f;

    for (int kt = 0; kt < 32; kt++) {
        int k0 = kt * 32;
        // A tile 128x32, tf32-quantized
#pragma unroll
        for (int p = 0; p < 4; p++) {
            int idx = p * 256 + tid;
            int row = idx >> 3;
            int col = (idx & 7) * 4;
            float4 v = *(const float4*)(Ab + (size_t)row * 1024 + k0 + col);
            As[row][col + 0] = tf32r(v.x); As[row][col + 1] = tf32r(v.y);
            As[row][col + 2] = tf32r(v.z); As[row][col + 3] = tf32r(v.w);
        }
        // B tiles 32x64 for both batches (transform + quantize)
#pragma unroll
        for (int q = 0; q < 2; q++) {
            const float* Bb = q ? Bb1 : Bb0;
#pragma unroll
            for (int p = 0; p < 2; p++) {
                int idx = p * 256 + tid;
                int row = idx >> 4;
                int col = (idx & 15) * 4;
                int n   = k0 + row;
                float4 v = *(const float4*)(Bb + (size_t)n * NKC + col);
                if (STAGE == 2) {
                    float a = g_a1[n], c = g_c1[n];
                    v.x = fmaxf(fmaf(a, v.x, c), 0.f);
                    v.y = fmaxf(fmaf(a, v.y, c), 0.f);
                    v.z = fmaxf(fmaf(a, v.z, c), 0.f);
                    v.w = fmaxf(fmaf(a, v.w, c), 0.f);
                }
                Bs[q][row][col + 0] = tf32r(v.x); Bs[q][row][col + 1] = tf32r(v.y);
                Bs[q][row][col + 2] = tf32r(v.z); Bs[q][row][col + 3] = tf32r(v.w);
            }
        }
        __syncthreads();

#pragma unroll
        for (int s = 0; s < 4; s++) {
            int kr = s * 8;
            uint32_t af[2][4];
#pragma unroll
            for (int mt = 0; mt < 2; mt++) {
                int o = warp_o * 32 + mt * 16;
                af[mt][0] = __float_as_uint(As[o + g    ][kr + tg    ]);
                af[mt][1] = __float_as_uint(As[o + g + 8][kr + tg    ]);
                af[mt][2] = __float_as_uint(As[o + g    ][kr + tg + 4]);
                af[mt][3] = __float_as_uint(As[o + g + 8][kr + tg + 4]);
            }
#pragma unroll
            for (int q = 0; q < 2; q++) {
                uint32_t bf[4][2];
#pragma unroll
                for (int nt = 0; nt < 4; nt++) {
                    int col = warp_n * 32 + nt * 8 + g;
                    bf[nt][0] = __float_as_uint(Bs[q][kr + tg    ][col]);
                    bf[nt][1] = __float_as_uint(Bs[q][kr + tg + 4][col]);
                }
#pragma unroll
                for (int mt = 0; mt < 2; mt++)
#pragma unroll
                    for (int nt = 0; nt < 4; nt++)
                        mma_tf32(acc[q][mt][nt], af[mt], bf[nt], acc[q][mt][nt]);
            }
        }
        __syncthreads();
    }

#pragma unroll
    for (int q = 0; q < 2; q++) {
        float* Cb = Cm + (size_t)(bz0 + q) * (NO * NKC) + (size_t)o0 * NKC + kc0;
#pragma unroll
        for (int mt = 0; mt < 2; mt++) {
            int row = warp_o * 32 + mt * 16 + g;
#pragma unroll
            for (int nt = 0; nt < 4; nt++) {
                int col = warp_n * 32 + nt * 8 + tg * 2;
                *(float2*)&Cb[(size_t)(row    ) * NKC + col] =
                    make_float2(acc[q][mt][nt][0], acc[q][mt][nt][1]);
                *(float2*)&Cb[(size_t)(row + 8) * NKC + col] =
                    make_float2(acc[q][mt][nt][2], acc[q][mt][nt][3]);
            }
        }
    }
}

// ---------------- BN stats per channel o: a = gamma*rsqrt(var+eps), c = beta - mean*a
__global__ void bn_stats_kernel(const float* __restrict__ gamma,
                                const float* __restrict__ beta, int which) {
    const float* Y = which ? g_y2 : g_y1;
    int o = blockIdx.x, tid = threadIdx.x;
    float s = 0.f, sq = 0.f;
    for (int j = tid; j < NB * NKC; j += 256) {
        int b = j / NKC, kc = j - b * NKC;
        float v = Y[((size_t)b * NO + o) * NKC + kc];
        s += v; sq = fmaf(v, v, sq);
    }
    __shared__ float ss[256], s2[256];
    ss[tid] = s; s2[tid] = sq;
    __syncthreads();
    for (int st = 128; st; st >>= 1) {
        if (tid < st) { ss[tid] += ss[tid + st]; s2[tid] += s2[tid + st]; }
        __syncthreads();
    }
    if (tid == 0) {
        float cnt  = (float)(NB * NKC);
        float mean = ss[0] / cnt;
        float var  = fmaxf(s2[0] / cnt - mean * mean, 0.f);
        float ai   = gamma[o] * rsqrtf(var + EPSN);
        if (which) { g_a2[o] = ai; g_c2[o] = beta[o] - mean * ai; }
        else       { g_a1[o] = ai; g_c1[o] = beta[o] - mean * ai; }
    }
}

// ---------------- out[b,o,c] = max_k relu(a2*y2 + c2) ----------------
__global__ void max_kernel(float* __restrict__ out) {
    int t = blockIdx.x * blockDim.x + threadIdx.x;
    int c = t & 63;
    int o = (t >> 6) & 1023;
    int b = t >> 16;
    const float* y = g_y2 + ((size_t)(b * NO + o)) * NKC + c;
    float a = g_a2[o], cc = g_c2[o];
    float m = -3.4e38f;
#pragma unroll
    for (int k = 0; k < NK; k++) m = fmaxf(m, fmaf(a, y[k * 64], cc));
    out[t] = fmaxf(m, 0.f);
}

// ---------------- launch ----------------
extern "C" void kernel_launch(void* const* d_in, const int* in_sizes, int n_in,
                              void* d_out, int out_size) {
    const float* x      = (const float*)d_in[0];
    const float* w1     = (const float*)d_in[1];
    // b1 = d_in[2], b2 = d_in[6]: zeros AND cancelled by BN mean-subtraction
    const float* gamma1 = (const float*)d_in[3];
    const float* beta1  = (const float*)d_in[4];
    const float* w2     = (const float*)d_in[5];
    const float* gamma2 = (const float*)d_in[7];
    const float* beta2  = (const float*)d_in[8];
    float* out = (float*)d_out;

    transpose_kernel<<<dim3(32, 2, 32), dim3(32, 8)>>>(x);
    xx_kernel<<<128, 256>>>(x);
    dist_kernel<<<dim3(136, 1, 32), 256>>>();
    topk_kernel<<<4096, 256>>>();
    gather_kernel<<<81920, 256>>>();
    gemm_mma_kernel<1><<<dim3(10, 8, 16), 256>>>(w1);
    bn_stats_kernel<<<1024, 256>>>(gamma1, beta1, 0);
    gemm_mma_kernel<2><<<dim3(10, 8, 16), 256>>>(w2);
    bn_stats_kernel<<<1024, 256>>>(gamma2, beta2, 1);
    max_kernel<<<8192, 256>>>(out);
}